// round 1
// baseline (speedup 1.0000x reference)
#include <cuda_runtime.h>

#define NB   8
#define NC   512
#define NHW  4096
#define NQKV 1536

// Scratch (no cudaMalloc allowed): qkv activations, reduction partials, channel scales.
__device__ float g_qkv[(size_t)NB * NHW * NQKV];   // 201 MB
__device__ float g_part[NB * 128 * 1024];          // per-(b,chunk) partial sums [know|mask]
__device__ float g_s[NB * 1024];                   // [b][0:512]=s_know, [b][512:1024]=0.7*s_mask

// ---------------------------------------------------------------------------
// GEMM1: qkv[b,t,j] = sum_c x[b,c,t] * Wq[c,j] + bq[j]
// A is K-major in gmem (x is (B,C,HW)); tile 64x64x16, 256 threads, 4x4 microtile.
// ---------------------------------------------------------------------------
__global__ __launch_bounds__(256) void k_gemm_qkv(
        const float* __restrict__ x, const float* __restrict__ Wq,
        const float* __restrict__ bq) {
    __shared__ float As[16][64];
    __shared__ float Bs[16][64];
    const int b   = blockIdx.z;
    const int tm0 = blockIdx.y * 64;
    const int n0  = blockIdx.x * 64;
    const int tid = threadIdx.x;
    const int tt  = tid & 63, ccb = tid >> 6;   // loader mapping
    const int tx  = tid & 15, ty  = tid >> 4;   // compute mapping

    float acc[4][4];
    #pragma unroll
    for (int i = 0; i < 4; i++)
        #pragma unroll
        for (int j = 0; j < 4; j++) acc[i][j] = 0.f;

    const float* xb = x  + (size_t)b * NC * NHW + tm0 + tt;
    const float* wb = Wq + n0 + tt;

    for (int kc = 0; kc < NC; kc += 16) {
        #pragma unroll
        for (int r = 0; r < 4; r++) {
            int cc = ccb * 4 + r;
            As[cc][tt] = xb[(size_t)(kc + cc) * NHW];
            Bs[cc][tt] = wb[(size_t)(kc + cc) * NQKV];
        }
        __syncthreads();
        #pragma unroll
        for (int k = 0; k < 16; k++) {
            float4 av = *(const float4*)&As[k][ty * 4];
            float4 bv = *(const float4*)&Bs[k][tx * 4];
            float a[4]  = {av.x, av.y, av.z, av.w};
            float bb[4] = {bv.x, bv.y, bv.z, bv.w};
            #pragma unroll
            for (int i = 0; i < 4; i++)
                #pragma unroll
                for (int j = 0; j < 4; j++) acc[i][j] += a[i] * bb[j];
        }
        __syncthreads();
    }

    float4 bias = *(const float4*)&bq[n0 + tx * 4];
    #pragma unroll
    for (int i = 0; i < 4; i++) {
        int row = tm0 + ty * 4 + i;
        float4 o = make_float4(acc[i][0] + bias.x, acc[i][1] + bias.y,
                               acc[i][2] + bias.z, acc[i][3] + bias.w);
        *(float4*)&g_qkv[((size_t)b * NHW + row) * NQKV + n0 + tx * 4] = o;
    }
}

// ---------------------------------------------------------------------------
// Normalize q,k per token (q stored back normalized); accumulate
// s_know[c] = sum_{t: m=0} kn[t,c]*v[t,c],  s_mask[c] = sum_{t: m=1} kn*v.
// Warp per token; deterministic block combine via shared staging (no atomics).
// grid = NB*128, 32 tokens per block.
// ---------------------------------------------------------------------------
__global__ __launch_bounds__(256) void k_normred(const float* __restrict__ mask) {
    const int b     = blockIdx.x >> 7;
    const int chunk = blockIdx.x & 127;
    const int warp  = threadIdx.x >> 5, lane = threadIdx.x & 31;

    float accK[16], accM[16];
    #pragma unroll
    for (int i = 0; i < 16; i++) { accK[i] = 0.f; accM[i] = 0.f; }

    #pragma unroll 1
    for (int it = 0; it < 4; it++) {
        const int t = chunk * 32 + warp * 4 + it;
        float* row = g_qkv + ((size_t)b * NHW + t) * NQKV;
        float q[16], kk[16], vv[16];
        float qss = 0.f, kss = 0.f;
        #pragma unroll
        for (int r = 0; r < 4; r++) {
            int c = (lane + 32 * r) * 4;
            float4 qa = *(const float4*)&row[c];
            float4 ka = *(const float4*)&row[512 + c];
            float4 va = *(const float4*)&row[1024 + c];
            q[r*4+0]=qa.x; q[r*4+1]=qa.y; q[r*4+2]=qa.z; q[r*4+3]=qa.w;
            kk[r*4+0]=ka.x; kk[r*4+1]=ka.y; kk[r*4+2]=ka.z; kk[r*4+3]=ka.w;
            vv[r*4+0]=va.x; vv[r*4+1]=va.y; vv[r*4+2]=va.z; vv[r*4+3]=va.w;
            qss += qa.x*qa.x + qa.y*qa.y + qa.z*qa.z + qa.w*qa.w;
            kss += ka.x*ka.x + ka.y*ka.y + ka.z*ka.z + ka.w*ka.w;
        }
        #pragma unroll
        for (int off = 16; off > 0; off >>= 1) {
            qss += __shfl_xor_sync(0xffffffffu, qss, off);
            kss += __shfl_xor_sync(0xffffffffu, kss, off);
        }
        const float rq = rsqrtf(qss), rk = rsqrtf(kss);
        const bool sel = mask[b * NHW + t] > 0.5f;
        #pragma unroll
        for (int i = 0; i < 16; i++) {
            float qn = q[i] * rq;
            q[i] = qn;
            float con = kk[i] * rk * vv[i];
            if (sel) accM[i] += con; else accK[i] += con;
        }
        #pragma unroll
        for (int r = 0; r < 4; r++) {
            int c = (lane + 32 * r) * 4;
            *(float4*)&row[c] = make_float4(q[r*4], q[r*4+1], q[r*4+2], q[r*4+3]);
        }
    }

    __shared__ float sh[8][1024];
    #pragma unroll
    for (int r = 0; r < 4; r++) {
        int c = (lane + 32 * r) * 4;
        *(float4*)&sh[warp][c]       = make_float4(accK[r*4], accK[r*4+1], accK[r*4+2], accK[r*4+3]);
        *(float4*)&sh[warp][512 + c] = make_float4(accM[r*4], accM[r*4+1], accM[r*4+2], accM[r*4+3]);
    }
    __syncthreads();
    float* part = g_part + (size_t)blockIdx.x * 1024;
    #pragma unroll
    for (int i = 0; i < 4; i++) {
        int ch = threadIdx.x + 256 * i;
        float s = 0.f;
        #pragma unroll
        for (int w = 0; w < 8; w++) s += sh[w][ch];   // fixed order: deterministic
        part[ch] = s;
    }
}

// Reduce the 128 chunk-partials per (b, channel) in fixed order. Fold 0.7 into s_mask.
__global__ void k_reduce_s() {
    const int idx = blockIdx.x * 256 + threadIdx.x;   // 0..8191
    const int b = idx >> 10, ch = idx & 1023;
    float s = 0.f;
    for (int c2 = 0; c2 < 128; c2++)
        s += g_part[((size_t)(b * 128 + c2)) * 1024 + ch];
    if (ch >= 512) s *= 0.7f;
    g_s[idx] = s;
}

// ---------------------------------------------------------------------------
// GEMM2: out[b,t,j] = sum_c (scale[b,t,c] * qn[b,t,c]) * Wo[c,j] + bo[j]
// scale folded into the A-tile loader: s_know[c] if m(t)=0 else 0.7*s_mask[c].
// ---------------------------------------------------------------------------
__global__ __launch_bounds__(256) void k_gemm_out(
        const float* __restrict__ mask, const float* __restrict__ Wo,
        const float* __restrict__ bo, float* __restrict__ out) {
    __shared__ float As[16][65];   // padded: loader writes column-strided
    __shared__ float Bs[16][64];
    __shared__ float msk[64];
    const int b   = blockIdx.z;
    const int tm0 = blockIdx.y * 64;
    const int n0  = blockIdx.x * 64;
    const int tid = threadIdx.x;
    const int tx  = tid & 15, ty = tid >> 4;

    if (tid < 64) msk[tid] = mask[b * NHW + tm0 + tid];
    __syncthreads();

    float acc[4][4];
    #pragma unroll
    for (int i = 0; i < 4; i++)
        #pragma unroll
        for (int j = 0; j < 4; j++) acc[i][j] = 0.f;

    const float* sb = g_s + b * 1024;
    const int cc  = tid & 15, ttb = tid >> 4;
    const int jj  = tid & 63, ccb = tid >> 6;

    for (int kc = 0; kc < NC; kc += 16) {
        #pragma unroll
        for (int r = 0; r < 4; r++) {
            int tt = ttb + r * 16;
            float qn = g_qkv[((size_t)b * NHW + tm0 + tt) * NQKV + kc + cc];
            float sv = (msk[tt] > 0.5f) ? sb[512 + kc + cc] : sb[kc + cc];
            As[cc][tt] = qn * sv;
        }
        #pragma unroll
        for (int r = 0; r < 4; r++) {
            int c2 = ccb * 4 + r;
            Bs[c2][jj] = Wo[(size_t)(kc + c2) * NC + n0 + jj];
        }
        __syncthreads();
        #pragma unroll
        for (int k = 0; k < 16; k++) {
            float a[4];
            #pragma unroll
            for (int i = 0; i < 4; i++) a[i] = As[k][ty * 4 + i];
            float4 bv = *(const float4*)&Bs[k][tx * 4];
            float bb[4] = {bv.x, bv.y, bv.z, bv.w};
            #pragma unroll
            for (int i = 0; i < 4; i++)
                #pragma unroll
                for (int j = 0; j < 4; j++) acc[i][j] += a[i] * bb[j];
        }
        __syncthreads();
    }

    float4 bias = *(const float4*)&bo[n0 + tx * 4];
    #pragma unroll
    for (int i = 0; i < 4; i++) {
        int row = tm0 + ty * 4 + i;
        float4 o = make_float4(acc[i][0] + bias.x, acc[i][1] + bias.y,
                               acc[i][2] + bias.z, acc[i][3] + bias.w);
        *(float4*)&out[((size_t)b * NHW + row) * NC + n0 + tx * 4] = o;
    }
}

extern "C" void kernel_launch(void* const* d_in, const int* in_sizes, int n_in,
                              void* d_out, int out_size) {
    const float* x    = (const float*)d_in[0];
    const float* mask = (const float*)d_in[1];
    const float* Wq   = (const float*)d_in[2];
    const float* bq   = (const float*)d_in[3];
    const float* Wo   = (const float*)d_in[4];
    const float* bo   = (const float*)d_in[5];
    float* out = (float*)d_out;

    k_gemm_qkv<<<dim3(NQKV / 64, NHW / 64, NB), 256>>>(x, Wq, bq);
    k_normred<<<NB * 128, 256>>>(mask);
    k_reduce_s<<<32, 256>>>();
    k_gemm_out<<<dim3(NC / 64, NHW / 64, NB), 256>>>(mask, Wo, bo, out);
}

// round 2
// speedup vs baseline: 1.6745x; 1.6745x over previous
#include <cuda_runtime.h>
#include <cuda_bf16.h>

#define NB   8
#define NC   512
#define NHW  4096
#define NQKV 1536

// ---------------- scratch (__device__ globals; no allocs allowed) ----------------
__device__ float g_qkv[(size_t)NB * NHW * NQKV];            // 201 MB fp32 qkv
__device__ float g_part[NB * 128 * 1024];
__device__ float g_s[NB * 1024];                            // [b][0:512]=s_know, [512:1024]=0.7*s_mask

__device__ __align__(16) __nv_bfloat16 g_xh[(size_t)NB * NHW * NC];   // x^T hi  [b][t][c]
__device__ __align__(16) __nv_bfloat16 g_xl[(size_t)NB * NHW * NC];   // x^T lo
__device__ __align__(16) __nv_bfloat16 g_wqh[(size_t)NQKV * NC];      // Wqkv^T hi [j][c]
__device__ __align__(16) __nv_bfloat16 g_wql[(size_t)NQKV * NC];
__device__ __align__(16) __nv_bfloat16 g_woh[(size_t)NC * NC];        // Wout^T hi [j][c]
__device__ __align__(16) __nv_bfloat16 g_wol[(size_t)NC * NC];
__device__ __align__(16) __nv_bfloat16 g_qah[(size_t)NB * NHW * NC];  // scaled qn hi [b][t][c]
__device__ __align__(16) __nv_bfloat16 g_qal[(size_t)NB * NHW * NC];

// ---------------------------------------------------------------------------
// Transpose [K][N] fp32 -> [N][K] bf16 hi/lo.  block (32,8), grid (N/32, K/32, batch)
// ---------------------------------------------------------------------------
__global__ void k_tsplit(const float* __restrict__ src,
                         __nv_bfloat16* __restrict__ dh,
                         __nv_bfloat16* __restrict__ dl,
                         int K, int N) {
    __shared__ float t[32][33];
    const int n0 = blockIdx.x * 32, k0 = blockIdx.y * 32;
    src += (size_t)blockIdx.z * K * N;
    dh  += (size_t)blockIdx.z * N * K;
    dl  += (size_t)blockIdx.z * N * K;
    const int tx = threadIdx.x, ty = threadIdx.y;
    #pragma unroll
    for (int r = 0; r < 4; r++)
        t[ty + r * 8][tx] = src[(size_t)(k0 + ty + r * 8) * N + n0 + tx];
    __syncthreads();
    #pragma unroll
    for (int r = 0; r < 4; r++) {
        float v = t[tx][ty + r * 8];
        __nv_bfloat16 h = __float2bfloat16(v);
        __nv_bfloat16 l = __float2bfloat16(v - __bfloat162float(h));
        size_t o = (size_t)(n0 + ty + r * 8) * K + k0 + tx;
        dh[o] = h;
        dl[o] = l;
    }
}

// ---------------------------------------------------------------------------
// bf16x3 tensor-core GEMM:
//   C[m][n] = sum_k (Ah+Al)[m][k] * (Bh+Bl)[n][k] + bias[n]   (hh + hl + lh terms)
// A: [M][K] bf16 (batched, strideA), B: [N][K] bf16 (shared), C fp32 (strideC).
// Tiles 128x128x16, 256 threads, warp grid 2(M)x4(N), warp tile 64x32.
// ---------------------------------------------------------------------------
__device__ __forceinline__ void mma16816(float* d, const unsigned* a, unsigned b0, unsigned b1) {
    asm volatile(
        "mma.sync.aligned.m16n8k16.row.col.f32.bf16.bf16.f32 "
        "{%0,%1,%2,%3}, {%4,%5,%6,%7}, {%8,%9}, {%0,%1,%2,%3};\n"
        : "+f"(d[0]), "+f"(d[1]), "+f"(d[2]), "+f"(d[3])
        : "r"(a[0]), "r"(a[1]), "r"(a[2]), "r"(a[3]), "r"(b0), "r"(b1));
}

#define PITCH 24   // bf16 elems per smem row (48B): conflict-free frag loads

__global__ __launch_bounds__(256) void k_gemm_bf3(
        const __nv_bfloat16* __restrict__ Ah, const __nv_bfloat16* __restrict__ Al,
        const __nv_bfloat16* __restrict__ Bh, const __nv_bfloat16* __restrict__ Bl,
        const float* __restrict__ bias, float* __restrict__ C,
        int Nd, size_t strideA, size_t strideC) {
    __shared__ __align__(16) __nv_bfloat16 smAh[2][128][PITCH];
    __shared__ __align__(16) __nv_bfloat16 smAl[2][128][PITCH];
    __shared__ __align__(16) __nv_bfloat16 smBh[2][128][PITCH];
    __shared__ __align__(16) __nv_bfloat16 smBl[2][128][PITCH];

    const int tid = threadIdx.x;
    const int m0 = blockIdx.y * 128, n0 = blockIdx.x * 128;
    const int wid = tid >> 5, lane = tid & 31;
    const int warp_m = (wid >> 2) * 64, warp_n = (wid & 3) * 32;
    const int fr = lane >> 2, fc2 = (lane & 3) * 2;

    // loader mapping: row = tid&127, k-half = (tid>>7)*8  (conflict-free 16B STS)
    const int lr = tid & 127, lk = (tid >> 7) * 8;
    const __nv_bfloat16* gAh = Ah + (size_t)blockIdx.z * strideA + (size_t)(m0 + lr) * NC + lk;
    const __nv_bfloat16* gAl = Al + (size_t)blockIdx.z * strideA + (size_t)(m0 + lr) * NC + lk;
    const __nv_bfloat16* gBh = Bh + (size_t)(n0 + lr) * NC + lk;
    const __nv_bfloat16* gBl = Bl + (size_t)(n0 + lr) * NC + lk;

    float acc[4][4][4];
    #pragma unroll
    for (int i = 0; i < 4; i++)
        #pragma unroll
        for (int j = 0; j < 4; j++)
            #pragma unroll
            for (int c = 0; c < 4; c++) acc[i][j][c] = 0.f;

    // prologue: stage 0
    {
        uint4 a_h = *(const uint4*)gAh;
        uint4 a_l = *(const uint4*)gAl;
        uint4 b_h = *(const uint4*)gBh;
        uint4 b_l = *(const uint4*)gBl;
        *(uint4*)&smAh[0][lr][lk] = a_h;
        *(uint4*)&smAl[0][lr][lk] = a_l;
        *(uint4*)&smBh[0][lr][lk] = b_h;
        *(uint4*)&smBl[0][lr][lk] = b_l;
    }
    __syncthreads();

    #pragma unroll 1
    for (int s = 0; s < NC / 16; s++) {
        uint4 na_h, na_l, nb_h, nb_l;
        if (s < NC / 16 - 1) {
            gAh += 16; gAl += 16; gBh += 16; gBl += 16;
            na_h = *(const uint4*)gAh;
            na_l = *(const uint4*)gAl;
            nb_h = *(const uint4*)gBh;
            nb_l = *(const uint4*)gBl;
        }
        const int buf = s & 1;

        unsigned fa_h[4][4], fa_l[4][4];
        #pragma unroll
        for (int i = 0; i < 4; i++) {
            int r = warp_m + i * 16 + fr;
            fa_h[i][0] = *(const unsigned*)&smAh[buf][r][fc2];
            fa_h[i][1] = *(const unsigned*)&smAh[buf][r + 8][fc2];
            fa_h[i][2] = *(const unsigned*)&smAh[buf][r][fc2 + 8];
            fa_h[i][3] = *(const unsigned*)&smAh[buf][r + 8][fc2 + 8];
            fa_l[i][0] = *(const unsigned*)&smAl[buf][r][fc2];
            fa_l[i][1] = *(const unsigned*)&smAl[buf][r + 8][fc2];
            fa_l[i][2] = *(const unsigned*)&smAl[buf][r][fc2 + 8];
            fa_l[i][3] = *(const unsigned*)&smAl[buf][r + 8][fc2 + 8];
        }
        #pragma unroll
        for (int j = 0; j < 4; j++) {
            int nn = warp_n + j * 8 + fr;
            unsigned bh0 = *(const unsigned*)&smBh[buf][nn][fc2];
            unsigned bh1 = *(const unsigned*)&smBh[buf][nn][fc2 + 8];
            unsigned bl0 = *(const unsigned*)&smBl[buf][nn][fc2];
            unsigned bl1 = *(const unsigned*)&smBl[buf][nn][fc2 + 8];
            #pragma unroll
            for (int i = 0; i < 4; i++) {
                mma16816(acc[i][j], fa_h[i], bh0, bh1);
                mma16816(acc[i][j], fa_h[i], bl0, bl1);
                mma16816(acc[i][j], fa_l[i], bh0, bh1);
            }
        }

        if (s < NC / 16 - 1) {
            __syncthreads();
            const int nb = (s + 1) & 1;
            *(uint4*)&smAh[nb][lr][lk] = na_h;
            *(uint4*)&smAl[nb][lr][lk] = na_l;
            *(uint4*)&smBh[nb][lr][lk] = nb_h;
            *(uint4*)&smBl[nb][lr][lk] = nb_l;
            __syncthreads();
        }
    }

    // epilogue: +bias, fp32 stores
    float* Cb = C + (size_t)blockIdx.z * strideC + (size_t)m0 * Nd + n0;
    #pragma unroll
    for (int i = 0; i < 4; i++)
        #pragma unroll
        for (int j = 0; j < 4; j++) {
            int r0 = warp_m + i * 16 + fr;
            int c0 = warp_n + j * 8 + fc2;
            float2 bv = *(const float2*)&bias[n0 + c0];
            *(float2*)&Cb[(size_t)r0 * Nd + c0] =
                make_float2(acc[i][j][0] + bv.x, acc[i][j][1] + bv.y);
            *(float2*)&Cb[(size_t)(r0 + 8) * Nd + c0] =
                make_float2(acc[i][j][2] + bv.x, acc[i][j][3] + bv.y);
        }
}

// ---------------------------------------------------------------------------
// Normalize q,k per token; accumulate masked/unmasked k*v partial sums.
// ---------------------------------------------------------------------------
__global__ __launch_bounds__(256) void k_normred(const float* __restrict__ mask) {
    const int b     = blockIdx.x >> 7;
    const int chunk = blockIdx.x & 127;
    const int warp  = threadIdx.x >> 5, lane = threadIdx.x & 31;

    float accK[16], accM[16];
    #pragma unroll
    for (int i = 0; i < 16; i++) { accK[i] = 0.f; accM[i] = 0.f; }

    #pragma unroll 1
    for (int it = 0; it < 4; it++) {
        const int t = chunk * 32 + warp * 4 + it;
        float* row = g_qkv + ((size_t)b * NHW + t) * NQKV;
        float q[16], kk[16], vv[16];
        float qss = 0.f, kss = 0.f;
        #pragma unroll
        for (int r = 0; r < 4; r++) {
            int c = (lane + 32 * r) * 4;
            float4 qa = *(const float4*)&row[c];
            float4 ka = *(const float4*)&row[512 + c];
            float4 va = *(const float4*)&row[1024 + c];
            q[r*4+0]=qa.x; q[r*4+1]=qa.y; q[r*4+2]=qa.z; q[r*4+3]=qa.w;
            kk[r*4+0]=ka.x; kk[r*4+1]=ka.y; kk[r*4+2]=ka.z; kk[r*4+3]=ka.w;
            vv[r*4+0]=va.x; vv[r*4+1]=va.y; vv[r*4+2]=va.z; vv[r*4+3]=va.w;
            qss += qa.x*qa.x + qa.y*qa.y + qa.z*qa.z + qa.w*qa.w;
            kss += ka.x*ka.x + ka.y*ka.y + ka.z*ka.z + ka.w*ka.w;
        }
        #pragma unroll
        for (int off = 16; off > 0; off >>= 1) {
            qss += __shfl_xor_sync(0xffffffffu, qss, off);
            kss += __shfl_xor_sync(0xffffffffu, kss, off);
        }
        const float rq = rsqrtf(qss), rk = rsqrtf(kss);
        const bool sel = mask[b * NHW + t] > 0.5f;
        #pragma unroll
        for (int i = 0; i < 16; i++) {
            float qn = q[i] * rq;
            q[i] = qn;
            float con = kk[i] * rk * vv[i];
            if (sel) accM[i] += con; else accK[i] += con;
        }
        #pragma unroll
        for (int r = 0; r < 4; r++) {
            int c = (lane + 32 * r) * 4;
            *(float4*)&row[c] = make_float4(q[r*4], q[r*4+1], q[r*4+2], q[r*4+3]);
        }
    }

    __shared__ float sh[8][1024];
    #pragma unroll
    for (int r = 0; r < 4; r++) {
        int c = (lane + 32 * r) * 4;
        *(float4*)&sh[warp][c]       = make_float4(accK[r*4], accK[r*4+1], accK[r*4+2], accK[r*4+3]);
        *(float4*)&sh[warp][512 + c] = make_float4(accM[r*4], accM[r*4+1], accM[r*4+2], accM[r*4+3]);
    }
    __syncthreads();
    float* part = g_part + (size_t)blockIdx.x * 1024;
    #pragma unroll
    for (int i = 0; i < 4; i++) {
        int ch = threadIdx.x + 256 * i;
        float s = 0.f;
        #pragma unroll
        for (int w = 0; w < 8; w++) s += sh[w][ch];
        part[ch] = s;
    }
}

__global__ void k_reduce_s() {
    const int idx = blockIdx.x * 256 + threadIdx.x;
    const int ch = idx & 1023;
    float s = 0.f;
    const int b = idx >> 10;
    for (int c2 = 0; c2 < 128; c2++)
        s += g_part[((size_t)(b * 128 + c2)) * 1024 + ch];
    if (ch >= 512) s *= 0.7f;
    g_s[idx] = s;
}

// ---------------------------------------------------------------------------
// qA[t][c] = qn[t][c] * (mask? 0.7*s_mask[c] : s_know[c])  -> bf16 hi/lo
// ---------------------------------------------------------------------------
__global__ void k_scaleq(const float* __restrict__ mask) {
    const size_t idx = ((size_t)blockIdx.x * 256 + threadIdx.x) * 4;
    const int bt = (int)(idx >> 9);
    const int c  = (int)(idx & 511);
    const float4 q = *(const float4*)&g_qkv[(size_t)bt * NQKV + c];
    const bool sel = mask[bt] > 0.5f;
    const float4 sv = *(const float4*)&g_s[(bt >> 12) * 1024 + (sel ? 512 : 0) + c];
    float v[4] = {q.x * sv.x, q.y * sv.y, q.z * sv.z, q.w * sv.w};
    union { __nv_bfloat16 b[4]; uint2 u; } H, L;
    #pragma unroll
    for (int i = 0; i < 4; i++) {
        H.b[i] = __float2bfloat16(v[i]);
        L.b[i] = __float2bfloat16(v[i] - __bfloat162float(H.b[i]));
    }
    *(uint2*)&g_qah[idx] = H.u;
    *(uint2*)&g_qal[idx] = L.u;
}

// ---------------------------------------------------------------------------
extern "C" void kernel_launch(void* const* d_in, const int* in_sizes, int n_in,
                              void* d_out, int out_size) {
    const float* x    = (const float*)d_in[0];
    const float* mask = (const float*)d_in[1];
    const float* Wq   = (const float*)d_in[2];
    const float* bq   = (const float*)d_in[3];
    const float* Wo   = (const float*)d_in[4];
    const float* bo   = (const float*)d_in[5];
    float* out = (float*)d_out;

    __nv_bfloat16 *xh, *xl, *wqh, *wql, *woh, *wol, *qah, *qal;
    float *qkvp, *biasq;
    cudaGetSymbolAddress((void**)&xh,  g_xh);
    cudaGetSymbolAddress((void**)&xl,  g_xl);
    cudaGetSymbolAddress((void**)&wqh, g_wqh);
    cudaGetSymbolAddress((void**)&wql, g_wql);
    cudaGetSymbolAddress((void**)&woh, g_woh);
    cudaGetSymbolAddress((void**)&wol, g_wol);
    cudaGetSymbolAddress((void**)&qah, g_qah);
    cudaGetSymbolAddress((void**)&qal, g_qal);
    cudaGetSymbolAddress((void**)&qkvp, g_qkv);
    (void)biasq;

    // prep: transpose + bf16 hi/lo split
    k_tsplit<<<dim3(NHW / 32, NC / 32, NB), dim3(32, 8)>>>(x, xh, xl, NC, NHW);
    k_tsplit<<<dim3(NQKV / 32, NC / 32, 1), dim3(32, 8)>>>(Wq, wqh, wql, NC, NQKV);
    k_tsplit<<<dim3(NC / 32, NC / 32, 1), dim3(32, 8)>>>(Wo, woh, wol, NC, NC);

    // GEMM1: qkv = xT @ WqT^T + bq   (M=4096/b, N=1536, K=512)
    k_gemm_bf3<<<dim3(NQKV / 128, NHW / 128, NB), 256>>>(
        xh, xl, wqh, wql, bq, qkvp,
        NQKV, (size_t)NHW * NC, (size_t)NHW * NQKV);

    k_normred<<<NB * 128, 256>>>(mask);
    k_reduce_s<<<32, 256>>>();
    k_scaleq<<<(NB * NHW * NC) / 1024, 256>>>(mask);

    // GEMM2: out = qA @ WoT^T + bo   (M=4096/b, N=512, K=512)
    k_gemm_bf3<<<dim3(NC / 128, NHW / 128, NB), 256>>>(
        qah, qal, woh, wol, bo, out,
        NC, (size_t)NHW * NC, (size_t)NHW * NC);
}

// round 3
// speedup vs baseline: 2.3270x; 1.3897x over previous
#include <cuda_runtime.h>
#include <cuda_bf16.h>

#define NB   8
#define NC   512
#define NHW  4096
#define NQKV 1536

#define KSTAGE      32
#define NSTAGES     3
#define ARR_BYTES   (128 * 64)              // one operand array: 128 rows x 64B
#define STAGE_BYTES (4 * ARR_BYTES)         // Ah, Al, Bh, Bl
#define SMEM_TOTAL  (NSTAGES * STAGE_BYTES) // 96 KB

// ---------------- scratch (__device__ globals; no allocs allowed) ----------------
__device__ float g_qkv[(size_t)NB * NHW * NQKV];
__device__ float g_part[NB * 128 * 1024];
__device__ float g_s[NB * 1024];

__device__ __align__(16) __nv_bfloat16 g_xh[(size_t)NB * NHW * NC];
__device__ __align__(16) __nv_bfloat16 g_xl[(size_t)NB * NHW * NC];
__device__ __align__(16) __nv_bfloat16 g_wqh[(size_t)NQKV * NC];
__device__ __align__(16) __nv_bfloat16 g_wql[(size_t)NQKV * NC];
__device__ __align__(16) __nv_bfloat16 g_woh[(size_t)NC * NC];
__device__ __align__(16) __nv_bfloat16 g_wol[(size_t)NC * NC];
__device__ __align__(16) __nv_bfloat16 g_qah[(size_t)NB * NHW * NC];
__device__ __align__(16) __nv_bfloat16 g_qal[(size_t)NB * NHW * NC];

// ---------------------------------------------------------------------------
// Transpose [K][N] fp32 -> [N][K] bf16 hi/lo.
// ---------------------------------------------------------------------------
__global__ void k_tsplit(const float* __restrict__ src,
                         __nv_bfloat16* __restrict__ dh,
                         __nv_bfloat16* __restrict__ dl,
                         int K, int N) {
    __shared__ float t[32][33];
    const int n0 = blockIdx.x * 32, k0 = blockIdx.y * 32;
    src += (size_t)blockIdx.z * K * N;
    dh  += (size_t)blockIdx.z * N * K;
    dl  += (size_t)blockIdx.z * N * K;
    const int tx = threadIdx.x, ty = threadIdx.y;
    #pragma unroll
    for (int r = 0; r < 4; r++)
        t[ty + r * 8][tx] = src[(size_t)(k0 + ty + r * 8) * N + n0 + tx];
    __syncthreads();
    #pragma unroll
    for (int r = 0; r < 4; r++) {
        float v = t[tx][ty + r * 8];
        __nv_bfloat16 h = __float2bfloat16(v);
        __nv_bfloat16 l = __float2bfloat16(v - __bfloat162float(h));
        size_t o = (size_t)(n0 + ty + r * 8) * K + k0 + tx;
        dh[o] = h;
        dl[o] = l;
    }
}

// ---------------------------------------------------------------------------
// PTX helpers
// ---------------------------------------------------------------------------
__device__ __forceinline__ void mma16816(float* d, const unsigned* a, unsigned b0, unsigned b1) {
    asm volatile(
        "mma.sync.aligned.m16n8k16.row.col.f32.bf16.bf16.f32 "
        "{%0,%1,%2,%3}, {%4,%5,%6,%7}, {%8,%9}, {%0,%1,%2,%3};\n"
        : "+f"(d[0]), "+f"(d[1]), "+f"(d[2]), "+f"(d[3])
        : "r"(a[0]), "r"(a[1]), "r"(a[2]), "r"(a[3]), "r"(b0), "r"(b1));
}
__device__ __forceinline__ void ldsm4(unsigned* r, unsigned addr) {
    asm volatile("ldmatrix.sync.aligned.m8n8.x4.shared.b16 {%0,%1,%2,%3}, [%4];\n"
        : "=r"(r[0]), "=r"(r[1]), "=r"(r[2]), "=r"(r[3]) : "r"(addr));
}
__device__ __forceinline__ void cpa16(unsigned sdst, const void* gsrc) {
    asm volatile("cp.async.cg.shared.global [%0], [%1], 16;\n" :: "r"(sdst), "l"(gsrc));
}
__device__ __forceinline__ void cp_commit() { asm volatile("cp.async.commit_group;\n"); }
__device__ __forceinline__ void cp_wait1()  { asm volatile("cp.async.wait_group 1;\n"); }

// swizzled smem byte address: row has 4 16B granules, granule ^= (row>>1)&3
__device__ __forceinline__ unsigned swaddr(unsigned base, int row, int g) {
    return base + row * 64 + ((g ^ ((row >> 1) & 3)) << 4);
}

// ---------------------------------------------------------------------------
// bf16x3 tensor GEMM, cp.async 3-stage pipeline + ldmatrix.
// C[m][n] = sum_k (Ah+Al)[m][k]*(Bh+Bl)[n][k] + bias[n]  (hh+hl+lh)
// Block tile 128x128, K-stage 32, 256 threads, warp grid 2(m)x4(n), warp 64x32.
// ---------------------------------------------------------------------------
__global__ __launch_bounds__(256) void k_gemm_bf3(
        const __nv_bfloat16* __restrict__ Ah, const __nv_bfloat16* __restrict__ Al,
        const __nv_bfloat16* __restrict__ Bh, const __nv_bfloat16* __restrict__ Bl,
        const float* __restrict__ bias, float* __restrict__ C,
        int Nd, size_t strideA, size_t strideC) {
    extern __shared__ __align__(16) char smem[];
    const unsigned smbase = (unsigned)__cvta_generic_to_shared(smem);

    const int tid = threadIdx.x;
    const int m0 = blockIdx.y * 128, n0 = blockIdx.x * 128;
    const int wid = tid >> 5, lane = tid & 31;
    const int warp_m = (wid >> 2) * 64, warp_n = (wid & 3) * 32;
    const int frow = lane & 15, fghalf = lane >> 4;

    // loader mapping: thread t -> row t>>1, k-half (t&1)
    const int lrow = tid >> 1, lg0 = (tid & 1) * 2;
    const __nv_bfloat16* gA_h = Ah + (size_t)blockIdx.z * strideA + (size_t)(m0 + lrow) * NC + lg0 * 8;
    const __nv_bfloat16* gA_l = Al + (size_t)blockIdx.z * strideA + (size_t)(m0 + lrow) * NC + lg0 * 8;
    const __nv_bfloat16* gB_h = Bh + (size_t)(n0 + lrow) * NC + lg0 * 8;
    const __nv_bfloat16* gB_l = Bl + (size_t)(n0 + lrow) * NC + lg0 * 8;

    float acc[4][4][4];
    #pragma unroll
    for (int i = 0; i < 4; i++)
        #pragma unroll
        for (int j = 0; j < 4; j++)
            #pragma unroll
            for (int c = 0; c < 4; c++) acc[i][j][c] = 0.f;

    // stage issue: 8 cp.asyncs per thread (2 per operand array)
    auto issue_stage = [&](int kt, int buf) {
        const unsigned sb = smbase + buf * STAGE_BYTES;
        const int koff = kt * KSTAGE;   // element offset along K
        #pragma unroll
        for (int g = 0; g < 2; g++) {
            cpa16(swaddr(sb + 0 * ARR_BYTES, lrow, lg0 + g), gA_h + koff + g * 8);
            cpa16(swaddr(sb + 1 * ARR_BYTES, lrow, lg0 + g), gA_l + koff + g * 8);
            cpa16(swaddr(sb + 2 * ARR_BYTES, lrow, lg0 + g), gB_h + koff + g * 8);
            cpa16(swaddr(sb + 3 * ARR_BYTES, lrow, lg0 + g), gB_l + koff + g * 8);
        }
    };

    issue_stage(0, 0); cp_commit();
    issue_stage(1, 1); cp_commit();

    const int KTILES = NC / KSTAGE;   // 16
    #pragma unroll 1
    for (int kt = 0; kt < KTILES; kt++) {
        cp_wait1();
        __syncthreads();
        if (kt + 2 < KTILES) issue_stage(kt + 2, (kt + 2) % NSTAGES);
        cp_commit();   // empty groups keep wait accounting uniform

        const unsigned sb = smbase + (kt % NSTAGES) * STAGE_BYTES;
        const unsigned sAh = sb, sAl = sb + ARR_BYTES;
        const unsigned sBh = sb + 2 * ARR_BYTES, sBl = sb + 3 * ARR_BYTES;

        #pragma unroll
        for (int ks = 0; ks < 2; ks++) {
            const int gk = ks * 2 + fghalf;
            unsigned ah[4][4], al[4][4], bhf[2][4], blf[2][4];
            #pragma unroll
            for (int i = 0; i < 4; i++) {
                ldsm4(ah[i], swaddr(sAh, warp_m + 16 * i + frow, gk));
                ldsm4(al[i], swaddr(sAl, warp_m + 16 * i + frow, gk));
            }
            #pragma unroll
            for (int jb = 0; jb < 2; jb++) {
                ldsm4(bhf[jb], swaddr(sBh, warp_n + 16 * jb + frow, gk));
                ldsm4(blf[jb], swaddr(sBl, warp_n + 16 * jb + frow, gk));
            }
            #pragma unroll
            for (int j = 0; j < 4; j++) {
                const int jb = j >> 1;
                const unsigned b0h = bhf[jb][j & 1], b1h = bhf[jb][2 + (j & 1)];
                const unsigned b0l = blf[jb][j & 1], b1l = blf[jb][2 + (j & 1)];
                #pragma unroll
                for (int i = 0; i < 4; i++) {
                    mma16816(acc[i][j], ah[i], b0h, b1h);
                    mma16816(acc[i][j], ah[i], b0l, b1l);
                    mma16816(acc[i][j], al[i], b0h, b1h);
                }
            }
        }
    }

    float* Cb = C + (size_t)blockIdx.z * strideC + (size_t)m0 * Nd + n0;
    const int fr = lane >> 2, fc2 = (lane & 3) * 2;
    #pragma unroll
    for (int i = 0; i < 4; i++)
        #pragma unroll
        for (int j = 0; j < 4; j++) {
            int r0 = warp_m + i * 16 + fr;
            int c0 = warp_n + j * 8 + fc2;
            float2 bv = *(const float2*)&bias[n0 + c0];
            *(float2*)&Cb[(size_t)r0 * Nd + c0] =
                make_float2(acc[i][j][0] + bv.x, acc[i][j][1] + bv.y);
            *(float2*)&Cb[(size_t)(r0 + 8) * Nd + c0] =
                make_float2(acc[i][j][2] + bv.x, acc[i][j][3] + bv.y);
        }
}

// ---------------------------------------------------------------------------
// Normalize q,k per token; accumulate masked/unmasked k*v partial sums.
// ---------------------------------------------------------------------------
__global__ __launch_bounds__(256) void k_normred(const float* __restrict__ mask) {
    const int b     = blockIdx.x >> 7;
    const int chunk = blockIdx.x & 127;
    const int warp  = threadIdx.x >> 5, lane = threadIdx.x & 31;

    float accK[16], accM[16];
    #pragma unroll
    for (int i = 0; i < 16; i++) { accK[i] = 0.f; accM[i] = 0.f; }

    #pragma unroll 1
    for (int it = 0; it < 4; it++) {
        const int t = chunk * 32 + warp * 4 + it;
        float* row = g_qkv + ((size_t)b * NHW + t) * NQKV;
        float q[16], kk[16], vv[16];
        float qss = 0.f, kss = 0.f;
        #pragma unroll
        for (int r = 0; r < 4; r++) {
            int c = (lane + 32 * r) * 4;
            float4 qa = *(const float4*)&row[c];
            float4 ka = *(const float4*)&row[512 + c];
            float4 va = *(const float4*)&row[1024 + c];
            q[r*4+0]=qa.x; q[r*4+1]=qa.y; q[r*4+2]=qa.z; q[r*4+3]=qa.w;
            kk[r*4+0]=ka.x; kk[r*4+1]=ka.y; kk[r*4+2]=ka.z; kk[r*4+3]=ka.w;
            vv[r*4+0]=va.x; vv[r*4+1]=va.y; vv[r*4+2]=va.z; vv[r*4+3]=va.w;
            qss += qa.x*qa.x + qa.y*qa.y + qa.z*qa.z + qa.w*qa.w;
            kss += ka.x*ka.x + ka.y*ka.y + ka.z*ka.z + ka.w*ka.w;
        }
        #pragma unroll
        for (int off = 16; off > 0; off >>= 1) {
            qss += __shfl_xor_sync(0xffffffffu, qss, off);
            kss += __shfl_xor_sync(0xffffffffu, kss, off);
        }
        const float rq = rsqrtf(qss), rk = rsqrtf(kss);
        const bool sel = mask[b * NHW + t] > 0.5f;
        #pragma unroll
        for (int i = 0; i < 16; i++) {
            float qn = q[i] * rq;
            q[i] = qn;
            float con = kk[i] * rk * vv[i];
            if (sel) accM[i] += con; else accK[i] += con;
        }
        #pragma unroll
        for (int r = 0; r < 4; r++) {
            int c = (lane + 32 * r) * 4;
            *(float4*)&row[c] = make_float4(q[r*4], q[r*4+1], q[r*4+2], q[r*4+3]);
        }
    }

    __shared__ float sh[8][1024];
    #pragma unroll
    for (int r = 0; r < 4; r++) {
        int c = (lane + 32 * r) * 4;
        *(float4*)&sh[warp][c]       = make_float4(accK[r*4], accK[r*4+1], accK[r*4+2], accK[r*4+3]);
        *(float4*)&sh[warp][512 + c] = make_float4(accM[r*4], accM[r*4+1], accM[r*4+2], accM[r*4+3]);
    }
    __syncthreads();
    float* part = g_part + (size_t)blockIdx.x * 1024;
    #pragma unroll
    for (int i = 0; i < 4; i++) {
        int ch = threadIdx.x + 256 * i;
        float s = 0.f;
        #pragma unroll
        for (int w = 0; w < 8; w++) s += sh[w][ch];
        part[ch] = s;
    }
}

__global__ void k_reduce_s() {
    const int idx = blockIdx.x * 256 + threadIdx.x;
    const int ch = idx & 1023;
    const int b = idx >> 10;
    float s = 0.f;
    for (int c2 = 0; c2 < 128; c2++)
        s += g_part[((size_t)(b * 128 + c2)) * 1024 + ch];
    if (ch >= 512) s *= 0.7f;
    g_s[idx] = s;
}

__global__ void k_scaleq(const float* __restrict__ mask) {
    const size_t idx = ((size_t)blockIdx.x * 256 + threadIdx.x) * 4;
    const int bt = (int)(idx >> 9);
    const int c  = (int)(idx & 511);
    const float4 q = *(const float4*)&g_qkv[(size_t)bt * NQKV + c];
    const bool sel = mask[bt] > 0.5f;
    const float4 sv = *(const float4*)&g_s[(bt >> 12) * 1024 + (sel ? 512 : 0) + c];
    float v[4] = {q.x * sv.x, q.y * sv.y, q.z * sv.z, q.w * sv.w};
    union { __nv_bfloat16 b[4]; uint2 u; } H, L;
    #pragma unroll
    for (int i = 0; i < 4; i++) {
        H.b[i] = __float2bfloat16(v[i]);
        L.b[i] = __float2bfloat16(v[i] - __bfloat162float(H.b[i]));
    }
    *(uint2*)&g_qah[idx] = H.u;
    *(uint2*)&g_qal[idx] = L.u;
}

// ---------------------------------------------------------------------------
extern "C" void kernel_launch(void* const* d_in, const int* in_sizes, int n_in,
                              void* d_out, int out_size) {
    const float* x    = (const float*)d_in[0];
    const float* mask = (const float*)d_in[1];
    const float* Wq   = (const float*)d_in[2];
    const float* bq   = (const float*)d_in[3];
    const float* Wo   = (const float*)d_in[4];
    const float* bo   = (const float*)d_in[5];
    float* out = (float*)d_out;

    __nv_bfloat16 *xh, *xl, *wqh, *wql, *woh, *wol, *qah, *qal;
    float* qkvp;
    cudaGetSymbolAddress((void**)&xh,  g_xh);
    cudaGetSymbolAddress((void**)&xl,  g_xl);
    cudaGetSymbolAddress((void**)&wqh, g_wqh);
    cudaGetSymbolAddress((void**)&wql, g_wql);
    cudaGetSymbolAddress((void**)&woh, g_woh);
    cudaGetSymbolAddress((void**)&wol, g_wol);
    cudaGetSymbolAddress((void**)&qah, g_qah);
    cudaGetSymbolAddress((void**)&qal, g_qal);
    cudaGetSymbolAddress((void**)&qkvp, g_qkv);

    cudaFuncSetAttribute(k_gemm_bf3,
                         cudaFuncAttributeMaxDynamicSharedMemorySize, SMEM_TOTAL);

    k_tsplit<<<dim3(NHW / 32, NC / 32, NB), dim3(32, 8)>>>(x, xh, xl, NC, NHW);
    k_tsplit<<<dim3(NQKV / 32, NC / 32, 1), dim3(32, 8)>>>(Wq, wqh, wql, NC, NQKV);
    k_tsplit<<<dim3(NC / 32, NC / 32, 1), dim3(32, 8)>>>(Wo, woh, wol, NC, NC);

    k_gemm_bf3<<<dim3(NQKV / 128, NHW / 128, NB), 256, SMEM_TOTAL>>>(
        xh, xl, wqh, wql, bq, qkvp,
        NQKV, (size_t)NHW * NC, (size_t)NHW * NQKV);

    k_normred<<<NB * 128, 256>>>(mask);
    k_reduce_s<<<32, 256>>>();
    k_scaleq<<<(NB * NHW * NC) / 1024, 256>>>(mask);

    k_gemm_bf3<<<dim3(NC / 128, NHW / 128, NB), 256, SMEM_TOTAL>>>(
        qah, qal, woh, wol, bo, out,
        NC, (size_t)NHW * NC, (size_t)NHW * NC);
}

// round 6
// speedup vs baseline: 2.8121x; 1.2084x over previous
#include <cuda_runtime.h>
#include <cuda.h>
#include <cuda_bf16.h>
#include <cstdint>

#define NB   8
#define NC   512
#define NHW  4096
#define NQKV 1536

#define KSTEP   64                     // K elems per stage = 128B rows (SW128)
#define KTILES  (NC / KSTEP)           // 8
#define OPB     (128 * 128)            // one operand tile: 128 rows x 128B = 16KB
#define STAGEB  (4 * OPB)              // Ah, Al, Bh, Bl = 64KB
#define NST     3
#define DSMEM   (NST * STAGEB + 1024)  // 192KB + align slack

// ---------------- scratch (__device__ globals; no allocs allowed) ----------------
__device__ float g_qkv[(size_t)NB * NHW * NQKV];
__device__ float g_part[NB * 128 * 1024];
__device__ float g_s[NB * 1024];

__device__ __align__(16) __nv_bfloat16 g_xh[(size_t)NB * NHW * NC];
__device__ __align__(16) __nv_bfloat16 g_xl[(size_t)NB * NHW * NC];
__device__ __align__(16) __nv_bfloat16 g_wqh[(size_t)NQKV * NC];
__device__ __align__(16) __nv_bfloat16 g_wql[(size_t)NQKV * NC];
__device__ __align__(16) __nv_bfloat16 g_woh[(size_t)NC * NC];
__device__ __align__(16) __nv_bfloat16 g_wol[(size_t)NC * NC];
__device__ __align__(16) __nv_bfloat16 g_qah[(size_t)NB * NHW * NC];
__device__ __align__(16) __nv_bfloat16 g_qal[(size_t)NB * NHW * NC];

// ---------------------------------------------------------------------------
// PTX helpers (TMA / mbarrier / mma / ldmatrix)
// ---------------------------------------------------------------------------
__device__ __forceinline__ uint32_t cvta_s(const void* p) {
    return (uint32_t)__cvta_generic_to_shared(p);
}
__device__ __forceinline__ void mbar_init(uint32_t a, uint32_t c) {
    asm volatile("mbarrier.init.shared.b64 [%0], %1;" :: "r"(a), "r"(c) : "memory");
}
__device__ __forceinline__ void mbar_expect(uint32_t a, uint32_t tx) {
    asm volatile("mbarrier.arrive.expect_tx.shared.b64 _, [%0], %1;" :: "r"(a), "r"(tx) : "memory");
}
__device__ __forceinline__ void mbar_arrive(uint32_t a) {
    asm volatile("mbarrier.arrive.shared.b64 _, [%0];" :: "r"(a) : "memory");
}
__device__ __forceinline__ void mbar_wait(uint32_t a, uint32_t ph) {
    asm volatile(
        "{\n\t.reg .pred P;\n"
        "W%=:\n\tmbarrier.try_wait.parity.shared.b64 P, [%0], %1, 0x989680;\n"
        "\t@P bra D%=;\n\tbra W%=;\nD%=:\n\t}"
        :: "r"(a), "r"(ph) : "memory");
}
__device__ __forceinline__ void tma3d(uint32_t sa, const CUtensorMap* tm,
                                      int cx, int cy, int cz, uint32_t mb) {
    asm volatile(
        "cp.async.bulk.tensor.3d.shared::cta.global.tile.mbarrier::complete_tx::bytes "
        "[%0], [%1, {%2, %3, %4}], [%5];"
        :: "r"(sa), "l"(tm), "r"(cx), "r"(cy), "r"(cz), "r"(mb) : "memory");
}
__device__ __forceinline__ void mma16816(float* d, const unsigned* a, unsigned b0, unsigned b1) {
    asm volatile(
        "mma.sync.aligned.m16n8k16.row.col.f32.bf16.bf16.f32 "
        "{%0,%1,%2,%3}, {%4,%5,%6,%7}, {%8,%9}, {%0,%1,%2,%3};\n"
        : "+f"(d[0]), "+f"(d[1]), "+f"(d[2]), "+f"(d[3])
        : "r"(a[0]), "r"(a[1]), "r"(a[2]), "r"(a[3]), "r"(b0), "r"(b1));
}
__device__ __forceinline__ void ldsm4(unsigned* r, uint32_t addr) {
    asm volatile("ldmatrix.sync.aligned.m8n8.x4.shared.b16 {%0,%1,%2,%3}, [%4];\n"
        : "=r"(r[0]), "=r"(r[1]), "=r"(r[2]), "=r"(r[3]) : "r"(addr));
}
// SW128 (TMA) swizzle inside a 128-row x 128B tile: granule g of row r
__device__ __forceinline__ uint32_t swoff(int row, int g) {
    return (uint32_t)(row * 128 + ((g ^ (row & 7)) << 4));
}

// ---------------------------------------------------------------------------
// bf16x3 mma.sync GEMM with TMA + mbarrier pipeline (no __syncthreads in loop).
// C[m][n] = sum_k (Ah+Al)[m][k]*(Bh+Bl)[n][k] + bias[n]   (hh + hl + lh)
// Tile 128x128, K-stage 64, 3 stages. 288 threads: warps 0-7 consume
// (warp grid 2m x 4n, warp tile 64x32), warp 8 produces (TMA).
// ---------------------------------------------------------------------------
__global__ __launch_bounds__(288, 1) void k_gemm_ws(
        const __grid_constant__ CUtensorMap tAh,
        const __grid_constant__ CUtensorMap tAl,
        const __grid_constant__ CUtensorMap tBh,
        const __grid_constant__ CUtensorMap tBl,
        const float* __restrict__ bias, float* __restrict__ C,
        int Nd, unsigned long long strideC) {
    extern __shared__ __align__(16) char dsm[];
    __shared__ __align__(8) long long mbars[6];   // full[0..2], empty[0..2]

    const int tid = threadIdx.x, wid = tid >> 5, lane = tid & 31;
    const int m0 = blockIdx.y * 128, n0 = blockIdx.x * 128, bz = blockIdx.z;
    const uint32_t tile0 = (cvta_s(dsm) + 1023u) & ~1023u;
    const uint32_t mb = cvta_s(mbars);

    if (tid == 0) {
        #pragma unroll
        for (int i = 0; i < NST; i++) {
            mbar_init(mb + i * 8, 1);             // full: 1 expect_tx arrival
            mbar_init(mb + (NST + i) * 8, 8);     // empty: 8 consumer warps
        }
    }
    __syncthreads();

    if (wid == 8) {
        // ---------------- producer ----------------
        if (lane == 0) {
            int st = 0;
            #pragma unroll 1
            for (int s = 0; s < KTILES; s++) {
                if (s >= NST) mbar_wait(mb + (NST + st) * 8, ((s / NST) - 1) & 1);
                const uint32_t base = tile0 + st * STAGEB;
                const uint32_t fb = mb + st * 8;
                mbar_expect(fb, STAGEB);
                tma3d(base,           &tAh, s * KSTEP, m0, bz, fb);
                tma3d(base + OPB,     &tAl, s * KSTEP, m0, bz, fb);
                tma3d(base + 2 * OPB, &tBh, s * KSTEP, n0, 0,  fb);
                tma3d(base + 3 * OPB, &tBl, s * KSTEP, n0, 0,  fb);
                if (++st == NST) st = 0;
            }
        }
        return;
    }

    // ---------------- consumers ----------------
    const int warp_m = (wid >> 2) * 64, warp_n = (wid & 3) * 32;
    const int frow = lane & 15, fgh = lane >> 4;

    float acc[4][4][4];
    #pragma unroll
    for (int i = 0; i < 4; i++)
        #pragma unroll
        for (int j = 0; j < 4; j++)
            #pragma unroll
            for (int c = 0; c < 4; c++) acc[i][j][c] = 0.f;

    int st = 0;
    #pragma unroll 1
    for (int kt = 0; kt < KTILES; kt++) {
        mbar_wait(mb + st * 8, (kt / NST) & 1);
        const uint32_t base = tile0 + st * STAGEB;
        const uint32_t sAh = base, sAl = base + OPB;
        const uint32_t sBh = base + 2 * OPB, sBl = base + 3 * OPB;

        #pragma unroll
        for (int k = 0; k < 4; k++) {
            const int g = 2 * k + fgh;
            unsigned ah[4][4], al[4][4], bh[2][4], bl[2][4];
            #pragma unroll
            for (int i = 0; i < 4; i++) {
                ldsm4(ah[i], sAh + swoff(warp_m + 16 * i + frow, g));
                ldsm4(al[i], sAl + swoff(warp_m + 16 * i + frow, g));
            }
            #pragma unroll
            for (int jb = 0; jb < 2; jb++) {
                ldsm4(bh[jb], sBh + swoff(warp_n + 16 * jb + frow, g));
                ldsm4(bl[jb], sBl + swoff(warp_n + 16 * jb + frow, g));
            }
            #pragma unroll
            for (int j = 0; j < 4; j++) {
                const int jb = j >> 1;
                const unsigned b0h = bh[jb][j & 1], b1h = bh[jb][2 + (j & 1)];
                const unsigned b0l = bl[jb][j & 1], b1l = bl[jb][2 + (j & 1)];
                #pragma unroll
                for (int i = 0; i < 4; i++) {
                    mma16816(acc[i][j], ah[i], b0h, b1h);
                    mma16816(acc[i][j], ah[i], b0l, b1l);
                    mma16816(acc[i][j], al[i], b0h, b1h);
                }
            }
        }
        if (lane == 0) mbar_arrive(mb + (NST + st) * 8);
        if (++st == NST) st = 0;
    }

    // epilogue: +bias, fp32 stores
    float* Cb = C + (size_t)bz * strideC + (size_t)m0 * Nd + n0;
    const int fr = lane >> 2, fc2 = (lane & 3) * 2;
    #pragma unroll
    for (int i = 0; i < 4; i++)
        #pragma unroll
        for (int j = 0; j < 4; j++) {
            int r0 = warp_m + i * 16 + fr;
            int c0 = warp_n + j * 8 + fc2;
            float2 bv = *(const float2*)&bias[n0 + c0];
            *(float2*)&Cb[(size_t)r0 * Nd + c0] =
                make_float2(acc[i][j][0] + bv.x, acc[i][j][1] + bv.y);
            *(float2*)&Cb[(size_t)(r0 + 8) * Nd + c0] =
                make_float2(acc[i][j][2] + bv.x, acc[i][j][3] + bv.y);
        }
}

// ---------------------------------------------------------------------------
// Transpose [K][N] fp32 -> [N][K] bf16 hi/lo.
// ---------------------------------------------------------------------------
__global__ void k_tsplit(const float* __restrict__ src,
                         __nv_bfloat16* __restrict__ dh,
                         __nv_bfloat16* __restrict__ dl,
                         int K, int N) {
    __shared__ float t[32][33];
    const int n0 = blockIdx.x * 32, k0 = blockIdx.y * 32;
    src += (size_t)blockIdx.z * K * N;
    dh  += (size_t)blockIdx.z * N * K;
    dl  += (size_t)blockIdx.z * N * K;
    const int tx = threadIdx.x, ty = threadIdx.y;
    #pragma unroll
    for (int r = 0; r < 4; r++)
        t[ty + r * 8][tx] = src[(size_t)(k0 + ty + r * 8) * N + n0 + tx];
    __syncthreads();
    #pragma unroll
    for (int r = 0; r < 4; r++) {
        float v = t[tx][ty + r * 8];
        __nv_bfloat16 h = __float2bfloat16(v);
        __nv_bfloat16 l = __float2bfloat16(v - __bfloat162float(h));
        size_t o = (size_t)(n0 + ty + r * 8) * K + k0 + tx;
        dh[o] = h;
        dl[o] = l;
    }
}

// ---------------------------------------------------------------------------
// Normalize q,k per token; accumulate masked/unmasked k*v partial sums.
// ---------------------------------------------------------------------------
__global__ __launch_bounds__(256) void k_normred(const float* __restrict__ mask) {
    const int b     = blockIdx.x >> 7;
    const int chunk = blockIdx.x & 127;
    const int warp  = threadIdx.x >> 5, lane = threadIdx.x & 31;

    float accK[16], accM[16];
    #pragma unroll
    for (int i = 0; i < 16; i++) { accK[i] = 0.f; accM[i] = 0.f; }

    #pragma unroll 1
    for (int it = 0; it < 4; it++) {
        const int t = chunk * 32 + warp * 4 + it;
        float* row = g_qkv + ((size_t)b * NHW + t) * NQKV;
        float q[16], kk[16], vv[16];
        float qss = 0.f, kss = 0.f;
        #pragma unroll
        for (int r = 0; r < 4; r++) {
            int c = (lane + 32 * r) * 4;
            float4 qa = *(const float4*)&row[c];
            float4 ka = *(const float4*)&row[512 + c];
            float4 va = *(const float4*)&row[1024 + c];
            q[r*4+0]=qa.x; q[r*4+1]=qa.y; q[r*4+2]=qa.z; q[r*4+3]=qa.w;
            kk[r*4+0]=ka.x; kk[r*4+1]=ka.y; kk[r*4+2]=ka.z; kk[r*4+3]=ka.w;
            vv[r*4+0]=va.x; vv[r*4+1]=va.y; vv[r*4+2]=va.z; vv[r*4+3]=va.w;
            qss += qa.x*qa.x + qa.y*qa.y + qa.z*qa.z + qa.w*qa.w;
            kss += ka.x*ka.x + ka.y*ka.y + ka.z*ka.z + ka.w*ka.w;
        }
        #pragma unroll
        for (int off = 16; off > 0; off >>= 1) {
            qss += __shfl_xor_sync(0xffffffffu, qss, off);
            kss += __shfl_xor_sync(0xffffffffu, kss, off);
        }
        const float rq = rsqrtf(qss), rk = rsqrtf(kss);
        const bool sel = mask[b * NHW + t] > 0.5f;
        #pragma unroll
        for (int i = 0; i < 16; i++) {
            float qn = q[i] * rq;
            q[i] = qn;
            float con = kk[i] * rk * vv[i];
            if (sel) accM[i] += con; else accK[i] += con;
        }
        #pragma unroll
        for (int r = 0; r < 4; r++) {
            int c = (lane + 32 * r) * 4;
            *(float4*)&row[c] = make_float4(q[r*4], q[r*4+1], q[r*4+2], q[r*4+3]);
        }
    }

    __shared__ float sh[8][1024];
    #pragma unroll
    for (int r = 0; r < 4; r++) {
        int c = (lane + 32 * r) * 4;
        *(float4*)&sh[warp][c]       = make_float4(accK[r*4], accK[r*4+1], accK[r*4+2], accK[r*4+3]);
        *(float4*)&sh[warp][512 + c] = make_float4(accM[r*4], accM[r*4+1], accM[r*4+2], accM[r*4+3]);
    }
    __syncthreads();
    float* part = g_part + (size_t)blockIdx.x * 1024;
    #pragma unroll
    for (int i = 0; i < 4; i++) {
        int ch = threadIdx.x + 256 * i;
        float s = 0.f;
        #pragma unroll
        for (int w = 0; w < 8; w++) s += sh[w][ch];
        part[ch] = s;
    }
}

__global__ void k_reduce_s() {
    const int idx = blockIdx.x * 256 + threadIdx.x;
    const int ch = idx & 1023;
    const int b = idx >> 10;
    float s = 0.f;
    for (int c2 = 0; c2 < 128; c2++)
        s += g_part[((size_t)(b * 128 + c2)) * 1024 + ch];
    if (ch >= 512) s *= 0.7f;
    g_s[idx] = s;
}

__global__ void k_scaleq(const float* __restrict__ mask) {
    const size_t idx = ((size_t)blockIdx.x * 256 + threadIdx.x) * 4;
    const int bt = (int)(idx >> 9);
    const int c  = (int)(idx & 511);
    const float4 q = *(const float4*)&g_qkv[(size_t)bt * NQKV + c];
    const bool sel = mask[bt] > 0.5f;
    const float4 sv = *(const float4*)&g_s[(bt >> 12) * 1024 + (sel ? 512 : 0) + c];
    float v[4] = {q.x * sv.x, q.y * sv.y, q.z * sv.z, q.w * sv.w};
    union { __nv_bfloat16 b[4]; uint2 u; } H, L;
    #pragma unroll
    for (int i = 0; i < 4; i++) {
        H.b[i] = __float2bfloat16(v[i]);
        L.b[i] = __float2bfloat16(v[i] - __bfloat162float(H.b[i]));
    }
    *(uint2*)&g_qah[idx] = H.u;
    *(uint2*)&g_qal[idx] = L.u;
}

// ---------------------------------------------------------------------------
// Host: tensormap construction via driver entry point (no -lcuda link needed)
// ---------------------------------------------------------------------------
typedef CUresult (CUDAAPI *PFN_encode)(
    CUtensorMap*, CUtensorMapDataType, cuuint32_t, void*,
    const cuuint64_t*, const cuuint64_t*, const cuuint32_t*, const cuuint32_t*,
    CUtensorMapInterleave, CUtensorMapSwizzle, CUtensorMapL2promotion,
    CUtensorMapFloatOOBfill);

static PFN_encode get_encoder() {
    static PFN_encode fn = nullptr;
    if (!fn) {
        void* p = nullptr;
        cudaDriverEntryPointQueryResult qr;
        cudaGetDriverEntryPointByVersion("cuTensorMapEncodeTiled", &p, 12000,
                                         cudaEnableDefault, &qr);
        fn = (PFN_encode)p;
    }
    return fn;
}

static void build_map(CUtensorMap* m, const void* ptr,
                      unsigned long long d1, unsigned long long d2) {
    cuuint64_t dims[3] = {NC, d1, d2};
    cuuint64_t st[2]   = {NC * 2ull, d1 * NC * 2ull};
    cuuint32_t box[3]  = {KSTEP, 128, 1};
    cuuint32_t es[3]   = {1, 1, 1};
    get_encoder()(m, CU_TENSOR_MAP_DATA_TYPE_BFLOAT16, 3, (void*)ptr,
                  dims, st, box, es,
                  CU_TENSOR_MAP_INTERLEAVE_NONE, CU_TENSOR_MAP_SWIZZLE_128B,
                  CU_TENSOR_MAP_L2_PROMOTION_L2_128B,
                  CU_TENSOR_MAP_FLOAT_OOB_FILL_NONE);
}

extern "C" void kernel_launch(void* const* d_in, const int* in_sizes, int n_in,
                              void* d_out, int out_size) {
    const float* x    = (const float*)d_in[0];
    const float* mask = (const float*)d_in[1];
    const float* Wq   = (const float*)d_in[2];
    const float* bq   = (const float*)d_in[3];
    const float* Wo   = (const float*)d_in[4];
    const float* bo   = (const float*)d_in[5];
    float* out = (float*)d_out;

    __nv_bfloat16 *xh, *xl, *wqh, *wql, *woh, *wol, *qah, *qal;
    float* qkvp;
    cudaGetSymbolAddress((void**)&xh,  g_xh);
    cudaGetSymbolAddress((void**)&xl,  g_xl);
    cudaGetSymbolAddress((void**)&wqh, g_wqh);
    cudaGetSymbolAddress((void**)&wql, g_wql);
    cudaGetSymbolAddress((void**)&woh, g_woh);
    cudaGetSymbolAddress((void**)&wol, g_wol);
    cudaGetSymbolAddress((void**)&qah, g_qah);
    cudaGetSymbolAddress((void**)&qal, g_qal);
    cudaGetSymbolAddress((void**)&qkvp, g_qkv);

    CUtensorMap mXh, mXl, mWqh, mWql, mQh, mQl, mWoh, mWol;
    build_map(&mXh,  xh,  NHW,  NB);
    build_map(&mXl,  xl,  NHW,  NB);
    build_map(&mWqh, wqh, NQKV, 1);
    build_map(&mWql, wql, NQKV, 1);
    build_map(&mQh,  qah, NHW,  NB);
    build_map(&mQl,  qal, NHW,  NB);
    build_map(&mWoh, woh, NC,   1);
    build_map(&mWol, wol, NC,   1);

    cudaFuncSetAttribute(k_gemm_ws,
                         cudaFuncAttributeMaxDynamicSharedMemorySize, DSMEM);

    k_tsplit<<<dim3(NHW / 32, NC / 32, NB), dim3(32, 8)>>>(x, xh, xl, NC, NHW);
    k_tsplit<<<dim3(NQKV / 32, NC / 32, 1), dim3(32, 8)>>>(Wq, wqh, wql, NC, NQKV);
    k_tsplit<<<dim3(NC / 32, NC / 32, 1), dim3(32, 8)>>>(Wo, woh, wol, NC, NC);

    // GEMM1: qkv = x^T @ Wqkv + bq   (M=4096/b, N=1536, K=512)
    k_gemm_ws<<<dim3(NQKV / 128, NHW / 128, NB), 288, DSMEM>>>(
        mXh, mXl, mWqh, mWql, bq, qkvp, NQKV, (unsigned long long)NHW * NQKV);

    k_normred<<<NB * 128, 256>>>(mask);
    k_reduce_s<<<32, 256>>>();
    k_scaleq<<<(NB * NHW * NC) / 1024, 256>>>(mask);

    // GEMM2: out = qA @ Wout + bo   (M=4096/b, N=512, K=512)
    k_gemm_ws<<<dim3(NC / 128, NHW / 128, NB), 288, DSMEM>>>(
        mQh, mQl, mWoh, mWol, bo, out, NC, (unsigned long long)NHW * NC);
}